// round 7
// baseline (speedup 1.0000x reference)
#include <cuda_runtime.h>
#include <cuda_bf16.h>
#include <cstdint>

#define B_DIM 32
#define C_DIM 512
#define N_DIM 1024   // H*W

// ---------------- device scratch (allocation-free) --------------------------
__device__ __align__(16) unsigned short g_wvh[64 * 512];    // Wv^T hi  [d][c]
__device__ __align__(16) unsigned short g_wvl[64 * 512];    // Wv^T lo
__device__ __align__(16) unsigned short g_wph[512 * 512];   // Wp^T hi  [c2][c]
__device__ __align__(16) unsigned short g_wpl[512 * 512];   // Wp^T lo
__device__ float g_bv[64];
__device__ __align__(16) unsigned g_vh[B_DIM * 1024 * 32];  // v hi bf16 pairs [b][n][d/2]
__device__ __align__(16) unsigned g_vl[B_DIM * 1024 * 32];  // v lo

// ---------------- helpers ----------------------------------------------------
__device__ __forceinline__ unsigned smem_u32(const void* p) {
    unsigned a;
    asm("{ .reg .u64 t; cvta.to.shared.u64 t, %1; cvt.u32.u64 %0, t; }" : "=r"(a) : "l"(p));
    return a;
}
__device__ __forceinline__ void ldm_x4(unsigned* d, unsigned addr) {
    asm volatile("ldmatrix.sync.aligned.m8n8.x4.shared.b16 {%0,%1,%2,%3}, [%4];"
                 : "=r"(d[0]), "=r"(d[1]), "=r"(d[2]), "=r"(d[3]) : "r"(addr));
}
__device__ __forceinline__ void mma_bf16(float* c, const unsigned* a, const unsigned* b) {
    asm volatile(
        "mma.sync.aligned.m16n8k16.row.col.f32.bf16.bf16.f32 "
        "{%0,%1,%2,%3}, {%4,%5,%6,%7}, {%8,%9}, {%0,%1,%2,%3};"
        : "+f"(c[0]), "+f"(c[1]), "+f"(c[2]), "+f"(c[3])
        : "r"(a[0]), "r"(a[1]), "r"(a[2]), "r"(a[3]), "r"(b[0]), "r"(b[1]));
}
__device__ __forceinline__ void cp16(unsigned dst, const void* src) {
    asm volatile("cp.async.cg.shared.global [%0], [%1], 16;" :: "r"(dst), "l"(src));
}
__device__ __forceinline__ void cp_commit() { asm volatile("cp.async.commit_group;" ::: "memory"); }
__device__ __forceinline__ void cp_wait0()  { asm volatile("cp.async.wait_group 0;" ::: "memory"); }
__device__ __forceinline__ void cp_wait1()  { asm volatile("cp.async.wait_group 1;" ::: "memory"); }

__device__ __forceinline__ void cvt_split_pair(float f0, float f1, unsigned& h, unsigned& l) {
    asm("cvt.rn.bf16x2.f32 %0, %1, %2;" : "=r"(h) : "f"(f1), "f"(f0));
    float r0 = f0 - __uint_as_float(h << 16);
    float r1 = f1 - __uint_as_float(h & 0xffff0000u);
    asm("cvt.rn.bf16x2.f32 %0, %1, %2;" : "=r"(l) : "f"(r1), "f"(r0));
}

// ---------------------------------------------------------------------------
// prep (single launch): blocks [0,128) -> Wv^T split + bias; [128,384) -> Wp^T
// ---------------------------------------------------------------------------
__global__ void prep_all(const float* __restrict__ Wqkv, const float* __restrict__ bqkv,
                         const float* __restrict__ Wp) {
    int bid = blockIdx.x, tid = threadIdx.x;
    if (bid < 128) {
        int idx = bid * 256 + tid;                 // 32768
        int d = idx & 63, c = idx >> 6;
        const float* p = Wqkv + (size_t)c * 1536 + 1024 + d;
        float s = 0.f;
        #pragma unroll
        for (int h = 0; h < 8; ++h) s += p[h * 64];
        s *= 0.125f;
        __nv_bfloat16 hi = __float2bfloat16(s);
        __nv_bfloat16 lo = __float2bfloat16(s - __bfloat162float(hi));
        g_wvh[d * 512 + c] = *(unsigned short*)&hi;
        g_wvl[d * 512 + c] = *(unsigned short*)&lo;
        if (idx < 64) {
            float t = 0.f;
            #pragma unroll
            for (int h = 0; h < 8; ++h) t += bqkv[1024 + h * 64 + idx];
            g_bv[idx] = t * 0.125f;
        }
    } else {
        __shared__ float th[32][33], tl[32][33];
        int t = bid - 128;                          // 256 tiles
        int c0 = (t & 15) * 32, c20 = (t >> 4) * 32;
        int tx = tid & 31, ty = tid >> 5;           // (32, 8)
        #pragma unroll
        for (int i = 0; i < 4; ++i) {
            int c = c0 + ty + i * 8;
            float s = Wp[(size_t)c * 512 + c20 + tx];
            float hi = __bfloat162float(__float2bfloat16(s));
            th[ty + i * 8][tx] = hi;
            tl[ty + i * 8][tx] = s - hi;
        }
        __syncthreads();
        #pragma unroll
        for (int i = 0; i < 4; ++i) {
            int c2 = c20 + ty + i * 8;
            __nv_bfloat16 hb = __float2bfloat16(th[tx][ty + i * 8]);
            __nv_bfloat16 lb = __float2bfloat16(tl[tx][ty + i * 8]);
            g_wph[(size_t)c2 * 512 + c0 + tx] = *(unsigned short*)&hb;
            g_wpl[(size_t)c2 * 512 + c0 + tx] = *(unsigned short*)&lb;
        }
    }
}

// ---------------- warp MMA stage -------------------------------------------
struct Frag { unsigned aoff[2]; unsigned boff[2]; };

template<int PITCHB>
__device__ __forceinline__ Frag make_frag(int lane, int mw, int nw, unsigned off_b) {
    Frag fr;
    const int j4 = lane >> 3, r8 = lane & 7;
    #pragma unroll
    for (int mi = 0; mi < 2; ++mi)
        fr.aoff[mi] = (mw * 32 + mi * 16 + (j4 & 1) * 8 + r8) * PITCHB + (j4 >> 1) * 16;
    const int g2 = (lane >> 4) & 1, c8 = (lane >> 3) & 1;
    #pragma unroll
    for (int j2 = 0; j2 < 2; ++j2)
        fr.boff[j2] = off_b + (nw * 32 + j2 * 16 + g2 * 8 + r8) * PITCHB + c8 * 16;
    return fr;
}

template<int KS, int AL, int BL>
__device__ __forceinline__ void mma_stage(unsigned base, const Frag& fr, float C[2][4][4]) {
    #pragma unroll
    for (int ks = 0; ks < KS; ++ks) {
        unsigned ah[2][4], al[2][4], bh[2][4], bl[2][4];
        #pragma unroll
        for (int mi = 0; mi < 2; ++mi) {
            ldm_x4(ah[mi], base + fr.aoff[mi] + ks * 32);
            ldm_x4(al[mi], base + fr.aoff[mi] + ks * 32 + AL);
        }
        #pragma unroll
        for (int j2 = 0; j2 < 2; ++j2) {
            ldm_x4(bh[j2], base + fr.boff[j2] + ks * 32);
            ldm_x4(bl[j2], base + fr.boff[j2] + ks * 32 + BL);
        }
        #pragma unroll
        for (int mi = 0; mi < 2; ++mi)
            #pragma unroll
            for (int ni = 0; ni < 4; ++ni) {
                const unsigned* bhp = &bh[ni >> 1][(ni & 1) * 2];
                const unsigned* blp = &bl[ni >> 1][(ni & 1) * 2];
                mma_bf16(C[mi][ni], ah[mi], bhp);
                mma_bf16(C[mi][ni], ah[mi], blp);
                mma_bf16(C[mi][ni], al[mi], bhp);
            }
    }
}

// ---------------------------------------------------------------------------
// GEMM1: tile 256(n) x 64(d), 512 thr (16 warps: 8m x 2n), K-chunk 64, 8 chunks
// 2 stages, pitch 144B. stage: Ah 256*144=36864 | Al | Bh 64*144=9216 | Bl
// ---------------------------------------------------------------------------
#define G1_AL 36864
#define G1_B  73728
#define G1_BL 9216
#define G1_STG 92160
#define G1_SMEM (2 * G1_STG)

__global__ void __launch_bounds__(512) gemm1_mma(const float* __restrict__ x) {
    extern __shared__ char smem[];
    const int tid = threadIdx.x, lane = tid & 31, wid = tid >> 5;
    const int mw = wid >> 1, nw = wid & 1;
    const int b = blockIdx.y, n0 = blockIdx.x * 256;
    const unsigned sb = smem_u32(smem);
    const Frag fr = make_frag<144>(lane, mw, nw, G1_B);

    const int m_ld = tid & 255, kb0 = tid >> 8;    // k-blocks kb0 + 2i, i=0..3
    const float* xb = x + (size_t)b * (C_DIM * N_DIM) + n0;

    float C[2][4][4] = {};
    float f[4][8];

    auto ldg_chunk = [&](int kc) {
        const float* xc = xb + (size_t)kc * 64 * N_DIM;
        #pragma unroll
        for (int i = 0; i < 4; ++i) {
            int k0 = (kb0 + 2 * i) * 8;
            #pragma unroll
            for (int j = 0; j < 8; ++j)
                f[i][j] = xc[(size_t)(k0 + j) * N_DIM + m_ld];
        }
    };
    auto issueB = [&](int kc, int st) {
        int r = tid >> 3, q = tid & 7;              // 64 rows x 8 quads
        size_t s = (size_t)r * 512 + kc * 64 + q * 8;
        unsigned doff = sb + st * G1_STG + G1_B + r * 144 + q * 16;
        cp16(doff, g_wvh + s);
        cp16(doff + G1_BL, g_wvl + s);
        cp_commit();
    };
    auto cvt_sts = [&](int st) {
        char* base = smem + st * G1_STG;
        #pragma unroll
        for (int i = 0; i < 4; ++i) {
            unsigned h[4], l[4];
            #pragma unroll
            for (int p = 0; p < 4; ++p)
                cvt_split_pair(f[i][2 * p], f[i][2 * p + 1], h[p], l[p]);
            unsigned off = m_ld * 144 + (kb0 + 2 * i) * 16;
            *(uint4*)(base + off) = make_uint4(h[0], h[1], h[2], h[3]);
            *(uint4*)(base + G1_AL + off) = make_uint4(l[0], l[1], l[2], l[3]);
        }
    };

    // prologue: chunk 0 staged, chunk 1 in registers
    ldg_chunk(0);
    issueB(0, 0);
    cvt_sts(0);
    ldg_chunk(1);

    for (int kc = 0; kc < 8; ++kc) {
        const int st = kc & 1, nst = st ^ 1;
        cp_wait0();
        __syncthreads();
        if (kc < 7) { cvt_sts(nst); issueB(kc + 1, nst); }
        if (kc < 6) ldg_chunk(kc + 2);
        mma_stage<4, G1_AL, G1_BL>(sb + st * G1_STG, fr, C);
    }

    // epilogue: add bias, split, store v
    const int gr = lane >> 2, gc2 = (lane & 3) * 2;
    #pragma unroll
    for (int mi = 0; mi < 2; ++mi) {
        int m = n0 + mw * 32 + mi * 16 + gr;
        unsigned base0 = (unsigned)(b * 1024 + m) * 32u;
        unsigned base1 = base0 + 8 * 32;
        #pragma unroll
        for (int ni = 0; ni < 4; ++ni) {
            int d = nw * 32 + ni * 8 + gc2;
            float bv0 = g_bv[d], bv1 = g_bv[d + 1];
            unsigned h, l;
            cvt_split_pair(C[mi][ni][0] + bv0, C[mi][ni][1] + bv1, h, l);
            g_vh[base0 + (d >> 1)] = h;
            g_vl[base0 + (d >> 1)] = l;
            cvt_split_pair(C[mi][ni][2] + bv0, C[mi][ni][3] + bv1, h, l);
            g_vh[base1 + (d >> 1)] = h;
            g_vl[base1 + (d >> 1)] = l;
        }
    }
}

// ---------------------------------------------------------------------------
// GEMM2: tile 128(r) x 128(c2), 512 thr (16 warps: 4m x 4n), K-chunk 64, 8 chunks
// 3 stages, pitch 144B. stage: Ah 128*144=18432 | Al | Bh | Bl -> 73728
// ---------------------------------------------------------------------------
#define G2_AL 18432
#define G2_B  36864
#define G2_BL 18432
#define G2_STG 73728
#define G2_SMEM (3 * G2_STG)

__global__ void __launch_bounds__(512) gemm2_mma(const float* __restrict__ bp,
                                                 float* __restrict__ out) {
    extern __shared__ char smem[];
    const int tid = threadIdx.x, lane = tid & 31, wid = tid >> 5;
    const int mw = wid >> 2, nw = wid & 3;
    const int b = blockIdx.y, c20 = blockIdx.x * 128;
    const unsigned sb = smem_u32(smem);
    const Frag fr = make_frag<144>(lane, mw, nw, G2_B);

    const unsigned short* vhb = (const unsigned short*)g_vh + (size_t)b * 65536;
    const unsigned short* vlb = (const unsigned short*)g_vl + (size_t)b * 65536;

    float C[2][4][4] = {};

    auto issue = [&](int kc, int st) {
        unsigned stb = sb + st * G2_STG;
        #pragma unroll
        for (int i = 0; i < 2; ++i) {
            int idx = tid * 2 + i;                 // 0..1023
            int r = idx >> 3, q = idx & 7;
            size_t s = (size_t)r * 512 + kc * 64 + q * 8;
            unsigned off = r * 144 + q * 16;
            cp16(stb + off, vhb + s);
            cp16(stb + off + G2_AL, vlb + s);
            size_t sB = (size_t)(c20 + r) * 512 + kc * 64 + q * 8;
            cp16(stb + G2_B + off, g_wph + sB);
            cp16(stb + G2_B + off + G2_BL, g_wpl + sB);
        }
        cp_commit();
    };

    issue(0, 0);
    issue(1, 1);

    for (int kc = 0; kc < 8; ++kc) {
        const int st = kc % 3;
        if (kc < 7) cp_wait1(); else cp_wait0();
        __syncthreads();
        if (kc < 6) issue(kc + 2, (kc + 2) % 3);
        mma_stage<4, G2_AL, G2_BL>(sb + st * G2_STG, fr, C);
    }
    __syncthreads();

    // epilogue: stage to smem [c2][r] with bias, then coalesced x8 broadcast
    float* Cs = (float*)smem;      // [128][132] floats = 67584 B
    const int gr = lane >> 2, gc2 = (lane & 3) * 2;
    #pragma unroll
    for (int mi = 0; mi < 2; ++mi) {
        int r = mw * 32 + mi * 16 + gr;
        #pragma unroll
        for (int ni = 0; ni < 4; ++ni) {
            int c2l = nw * 32 + ni * 8 + gc2;
            float b0 = __ldg(bp + c20 + c2l), b1 = __ldg(bp + c20 + c2l + 1);
            Cs[c2l * 132 + r]           = C[mi][ni][0] + b0;
            Cs[(c2l + 1) * 132 + r]     = C[mi][ni][1] + b1;
            Cs[c2l * 132 + r + 8]       = C[mi][ni][2] + b0;
            Cs[(c2l + 1) * 132 + r + 8] = C[mi][ni][3] + b1;
        }
    }
    __syncthreads();

    float* ob = out + (size_t)b * (C_DIM * N_DIM) + (size_t)c20 * N_DIM;
    const int f4 = tid & 31, sub = tid >> 5;
    #pragma unroll 4
    for (int i = 0; i < 64; ++i) {
        int rowid = i * 16 + sub;               // 1024 row-writes
        int c2l = rowid >> 3, mrep = rowid & 7;
        float4 v = *(float4*)&Cs[c2l * 132 + f4 * 4];
        *(float4*)(ob + (size_t)c2l * N_DIM + mrep * 128 + f4 * 4) = v;
    }
}

// ---------------------------------------------------------------------------
extern "C" void kernel_launch(void* const* d_in, const int* in_sizes, int n_in,
                              void* d_out, int out_size) {
    const float* x    = (const float*)d_in[0];
    const float* Wqkv = (const float*)d_in[1];
    const float* bqkv = (const float*)d_in[2];
    const float* Wp   = (const float*)d_in[3];
    const float* bp   = (const float*)d_in[4];
    float* out = (float*)d_out;

    cudaFuncSetAttribute(gemm1_mma, cudaFuncAttributeMaxDynamicSharedMemorySize, G1_SMEM);
    cudaFuncSetAttribute(gemm2_mma, cudaFuncAttributeMaxDynamicSharedMemorySize, G2_SMEM);

    prep_all<<<384, 256>>>(Wqkv, bqkv, Wp);
    gemm1_mma<<<dim3(4, B_DIM), 512, G1_SMEM>>>(x);
    gemm2_mma<<<dim3(4, B_DIM), 512, G2_SMEM>>>(bp, out);
}